// round 10
// baseline (speedup 1.0000x reference)
#include <cuda_runtime.h>
#include <cuda_fp16.h>
#include <math_constants.h>
#include <cstdint>

#define N_NODES 100000
#define N_EDGES 1600000
#define IN_DIM 256
#define HEADS 4
#define OUT_DIM 32
#define FEAT_DIM 128
#define NEG_SLOPE 0.2f

#define SCAN_B 1024
#define NB ((N_NODES + SCAN_B - 1) / SCAN_B)   // 98
#define NTILES ((N_NODES + 127) / 128)         // 782
#define GEMM_GRID 148

// ---------------- scratch ---------------------------------------------------
__device__ __half g_feath[(size_t)N_NODES * FEAT_DIM];
__device__ float g_el[N_NODES * HEADS];
__device__ float g_er[N_NODES * HEADS];
__device__ int   g_deg[N_NODES];
__device__ int   g_off[N_NODES + 1];
__device__ int   g_cur[N_NODES];
__device__ int   g_esrc[N_EDGES];
__device__ int   g_bsums[128];

// ---------------- helpers ---------------------------------------------------
__device__ __forceinline__ uint32_t smem_u32(const void* p) {
    uint32_t a;
    asm("{ .reg .u64 t; cvta.to.shared.u64 t, %1; cvt.u32.u64 %0, t; }" : "=r"(a) : "l"(p));
    return a;
}
__device__ __forceinline__ void ldm_x4(uint32_t* r, uint32_t addr) {
    asm volatile("ldmatrix.sync.aligned.m8n8.x4.shared.b16 {%0,%1,%2,%3}, [%4];"
        : "=r"(r[0]), "=r"(r[1]), "=r"(r[2]), "=r"(r[3]) : "r"(addr));
}
__device__ __forceinline__ void ldm_x2(uint32_t* r, uint32_t addr) {
    asm volatile("ldmatrix.sync.aligned.m8n8.x2.shared.b16 {%0,%1}, [%2];"
        : "=r"(r[0]), "=r"(r[1]) : "r"(addr));
}
__device__ __forceinline__ void mma_f16(float* c, const uint32_t* a, const uint32_t* b) {
    asm volatile("mma.sync.aligned.m16n8k16.row.col.f32.f16.f16.f32 "
        "{%0,%1,%2,%3}, {%4,%5,%6,%7}, {%8,%9}, {%0,%1,%2,%3};"
        : "+f"(c[0]), "+f"(c[1]), "+f"(c[2]), "+f"(c[3])
        : "r"(a[0]), "r"(a[1]), "r"(a[2]), "r"(a[3]), "r"(b[0]), "r"(b[1]));
}

// ---------------- persistent single-fp16 HMMA GEMM --------------------------
// C = fp16(A) * fp16(W); fp32 MMA accumulate. Quantization error ~4e-4 total
// (A-quant + W-quant + fp16 feat storage), within 1e-3 budget.
#define B_STRIDE 264
#define A_STRIDE 40
#define SM_B  0
#define SM_AH (128 * B_STRIDE * 2)                 // 67584
#define SM_ALS (SM_AH + 2 * 128 * A_STRIDE * 2)    // +20480
#define SM_ARS (SM_ALS + 512)
#define GEMM_SMEM (SM_ARS + 512)                   // ~89 KB

__device__ __forceinline__ void cvt16h(const float4* f, uint32_t* hw) {
    const float* ff = (const float*)f;
#pragma unroll
    for (int j = 0; j < 8; j++) {
        __half2 hp = __floats2half2_rn(ff[2 * j], ff[2 * j + 1]);
        hw[j] = *reinterpret_cast<uint32_t*>(&hp);
    }
}

__global__ __launch_bounds__(256, 1) void gemm_mma_kernel(const float* __restrict__ A,
                                                          const float* __restrict__ W,
                                                          const float* __restrict__ attn_l,
                                                          const float* __restrict__ attn_r) {
    extern __shared__ char smem[];
    __half* Bs = (__half*)(smem + SM_B);
    float* al_s = (float*)(smem + SM_ALS);
    float* ar_s = (float*)(smem + SM_ARS);

    const int tid = threadIdx.x;
    const int wid = tid >> 5;
    const int lane = tid & 31;
    const int warp_m = wid >> 1;
    const int warp_n = wid & 1;

    // ---- W load + fp16 convert into resident smem (once per CTA) ----
    for (int idx = tid; idx < IN_DIM * FEAT_DIM; idx += 256) {
        int k = idx >> 7, n = idx & 127;
        Bs[n * B_STRIDE + k] = __float2half_rn(W[idx]);
    }
    if (tid < 128) { al_s[tid] = attn_l[tid]; ar_s[tid] = attn_r[tid]; }

    const int ld_row = tid >> 1;
    const int ld_koff = (tid & 1) * 16;

    const uint32_t ah_b = smem_u32(smem + SM_AH);
    const uint32_t b_b  = smem_u32(smem + SM_B);
    const uint32_t abuf_bytes = 128 * A_STRIDE * 2;
    __syncthreads();

    for (int tile = blockIdx.x; tile < NTILES; tile += GEMM_GRID) {
        const int blockRow = tile * 128;
        int grow = blockRow + ld_row;
        if (grow >= N_NODES) grow = N_NODES - 1;
        const float4* aptr = (const float4*)(A + (size_t)grow * IN_DIM + ld_koff);

        float c[2][8][4];
#pragma unroll
        for (int mt = 0; mt < 2; mt++)
#pragma unroll
            for (int nt = 0; nt < 8; nt++)
#pragma unroll
                for (int j = 0; j < 4; j++) c[mt][nt][j] = 0.f;

        // ---- prologue: chunk 0 -> buf 0 ----
        {
            float4 f[4];
#pragma unroll
            for (int j = 0; j < 4; j++) f[j] = aptr[j];
            uint32_t hw[8];
            cvt16h(f, hw);
            __half* Ah0 = (__half*)(smem + SM_AH);
            *(uint4*)&Ah0[ld_row * A_STRIDE + ld_koff]     = make_uint4(hw[0], hw[1], hw[2], hw[3]);
            *(uint4*)&Ah0[ld_row * A_STRIDE + ld_koff + 8] = make_uint4(hw[4], hw[5], hw[6], hw[7]);
        }
        __syncthreads();

        for (int kc = 0; kc < 8; kc++) {
            float4 fn[4];
            if (kc < 7) {
#pragma unroll
                for (int j = 0; j < 4; j++) fn[j] = aptr[(kc + 1) * 8 + j];
            }
            const uint32_t abase_h = ah_b + (kc & 1) * abuf_bytes;

#pragma unroll
            for (int ks = 0; ks < 2; ks++) {
                const int k0 = ks * 16;
                uint32_t ah[2][4];
#pragma unroll
                for (int mt = 0; mt < 2; mt++) {
                    int r = warp_m * 32 + mt * 16 + (lane & 15);
                    int cc = k0 + ((lane >> 4) & 1) * 8;
                    uint32_t off = (uint32_t)(r * A_STRIDE + cc) * 2;
                    ldm_x4(ah[mt], abase_h + off);
                }
                uint32_t bf[8][2];
#pragma unroll
                for (int nt = 0; nt < 8; nt++) {
                    int n = warp_n * 64 + nt * 8 + (lane & 7);
                    int cc = kc * 32 + k0 + ((lane >> 3) & 1) * 8;
                    uint32_t off = (uint32_t)(n * B_STRIDE + cc) * 2;
                    ldm_x2(bf[nt], b_b + off);
                }
#pragma unroll
                for (int mt = 0; mt < 2; mt++)
#pragma unroll
                    for (int nt = 0; nt < 8; nt++) {
                        mma_f16(c[mt][nt], ah[mt], bf[nt]);
                    }
            }

            if (kc < 7) {
                uint32_t hw[8];
                cvt16h(fn, hw);
                __half* Ahn = (__half*)(smem + SM_AH + ((kc + 1) & 1) * abuf_bytes);
                *(uint4*)&Ahn[ld_row * A_STRIDE + ld_koff]     = make_uint4(hw[0], hw[1], hw[2], hw[3]);
                *(uint4*)&Ahn[ld_row * A_STRIDE + ld_koff + 8] = make_uint4(hw[4], hw[5], hw[6], hw[7]);
            }
            __syncthreads();
        }

        // ---- epilogue: store feat (fp16) + fused el/er (fp32) ----
#pragma unroll
        for (int mt = 0; mt < 2; mt++) {
            float el_[2][2] = {{0.f, 0.f}, {0.f, 0.f}};
            float er_[2][2] = {{0.f, 0.f}, {0.f, 0.f}};
            int row0 = blockRow + warp_m * 32 + mt * 16 + (lane >> 2);
#pragma unroll
            for (int nt = 0; nt < 8; nt++) {
                int hl = nt >> 2;
                int col = warp_n * 64 + nt * 8 + (lane & 3) * 2;
                float c0 = c[mt][nt][0], c1 = c[mt][nt][1];
                float c2 = c[mt][nt][2], c3 = c[mt][nt][3];
                float a0 = al_s[col], a1 = al_s[col + 1];
                float r0 = ar_s[col], r1 = ar_s[col + 1];
                el_[0][hl] += c0 * a0 + c1 * a1;
                er_[0][hl] += c0 * r0 + c1 * r1;
                el_[1][hl] += c2 * a0 + c3 * a1;
                er_[1][hl] += c2 * r0 + c3 * r1;
                if (row0 < N_NODES)
                    *(__half2*)&g_feath[(size_t)row0 * FEAT_DIM + col] = __floats2half2_rn(c0, c1);
                if (row0 + 8 < N_NODES)
                    *(__half2*)&g_feath[(size_t)(row0 + 8) * FEAT_DIM + col] = __floats2half2_rn(c2, c3);
            }
#pragma unroll
            for (int rh = 0; rh < 2; rh++)
#pragma unroll
                for (int hl = 0; hl < 2; hl++) {
                    float v = el_[rh][hl];
                    float w = er_[rh][hl];
                    v += __shfl_xor_sync(0xffffffffu, v, 1);
                    v += __shfl_xor_sync(0xffffffffu, v, 2);
                    w += __shfl_xor_sync(0xffffffffu, w, 1);
                    w += __shfl_xor_sync(0xffffffffu, w, 2);
                    int row = row0 + rh * 8;
                    if ((lane & 3) == 0 && row < N_NODES) {
                        g_el[row * HEADS + warp_n * 2 + hl] = v;
                        g_er[row * HEADS + warp_n * 2 + hl] = w;
                    }
                }
        }
    }
}

// ---------------- CSR build ------------------------------------------------
__global__ void hist_kernel(const int* __restrict__ dst) {
    int i = blockIdx.x * blockDim.x + threadIdx.x;
    if (i < N_EDGES / 4) {
        int4 d = ((const int4*)dst)[i];
        atomicAdd(&g_deg[d.x], 1);
        atomicAdd(&g_deg[d.y], 1);
        atomicAdd(&g_deg[d.z], 1);
        atomicAdd(&g_deg[d.w], 1);
    }
}

__global__ __launch_bounds__(SCAN_B) void scan1_kernel() {
    __shared__ int wsum[32];
    int i = blockIdx.x * SCAN_B + threadIdx.x;
    int lane = threadIdx.x & 31;
    int wid = threadIdx.x >> 5;
    int v = (i < N_NODES) ? g_deg[i] : 0;
    int x = v;
#pragma unroll
    for (int o = 1; o < 32; o <<= 1) {
        int y = __shfl_up_sync(0xffffffffu, x, o);
        if (lane >= o) x += y;
    }
    if (lane == 31) wsum[wid] = x;
    __syncthreads();
    if (threadIdx.x < 32) {
        int w = wsum[threadIdx.x];
#pragma unroll
        for (int o = 1; o < 32; o <<= 1) {
            int y = __shfl_up_sync(0xffffffffu, w, o);
            if ((int)threadIdx.x >= o) w += y;
        }
        wsum[threadIdx.x] = w;
    }
    __syncthreads();
    int base = wid ? wsum[wid - 1] : 0;
    int incl = x + base;
    if (i < N_NODES) g_off[i] = incl;
    if (threadIdx.x == SCAN_B - 1) g_bsums[blockIdx.x] = incl;
}

// scan3 with inlined block-sums scan (replaces the old single-block scan2):
// every block redundantly computes the 98-element prefix of g_bsums in smem.
__global__ void scan3_kernel() {
    __shared__ int bpre[128];
    __shared__ int wtot[4];
    int t = threadIdx.x;
    int lane = t & 31;
    int w = t >> 5;
    int x = 0;
    if (t < 128) {
        x = (t < NB) ? g_bsums[t] : 0;
#pragma unroll
        for (int o = 1; o < 32; o <<= 1) {
            int y = __shfl_up_sync(0xffffffffu, x, o);
            if (lane >= o) x += y;
        }
        if (lane == 31) wtot[w] = x;
    }
    __syncthreads();
    if (t < 128) {
        int base = 0;
        for (int ww = 0; ww < w; ww++) base += wtot[ww];
        bpre[t] = x + base;
    }
    __syncthreads();
    int i = blockIdx.x * blockDim.x + t;
    if (i < N_NODES) {
        int b = i >> 10;
        int add = b ? bpre[b - 1] : 0;
        int incl = g_off[i] + add;
        int excl = incl - g_deg[i];
        g_off[i] = excl;
        g_cur[i] = excl;
        if (i == 0) g_off[N_NODES] = bpre[NB - 1];
    }
}

__global__ void scatter_kernel(const int* __restrict__ dst, const int* __restrict__ src) {
    int i = blockIdx.x * blockDim.x + threadIdx.x;
    if (i < N_EDGES / 4) {
        int4 d = ((const int4*)dst)[i];
        int4 s = ((const int4*)src)[i];
        g_esrc[atomicAdd(&g_cur[d.x], 1)] = s.x;
        g_esrc[atomicAdd(&g_cur[d.y], 1)] = s.y;
        g_esrc[atomicAdd(&g_cur[d.z], 1)] = s.z;
        g_esrc[atomicAdd(&g_cur[d.w], 1)] = s.w;
    }
}

// ---------------- fused single-pass softmax + aggregation (8-deep MLP) -----
__device__ __forceinline__ float4 ldh4(const __half* p) {
    uint2 u = *(const uint2*)p;
    __half2 h0 = *reinterpret_cast<__half2*>(&u.x);
    __half2 h1 = *reinterpret_cast<__half2*>(&u.y);
    float2 f0 = __half22float2(h0);
    float2 f1 = __half22float2(h1);
    return make_float4(f0.x, f0.y, f1.x, f1.y);
}

__global__ __launch_bounds__(256) void aggregate_kernel(float* __restrict__ out) {
    int n = (blockIdx.x * blockDim.x + threadIdx.x) >> 5;
    int lane = threadIdx.x & 31;
    if (n >= N_NODES) return;
    int h = lane >> 3;
    int q = lane & 7;

    int begin = g_off[n];
    int end = g_off[n + 1];
    float erh = g_er[n * HEADS + h];

    float4 acc = make_float4(0.f, 0.f, 0.f, 0.f);
    float denom = 0.f;
    int i = begin;
    for (; i + 8 <= end; i += 8) {
        int s[8];
#pragma unroll
        for (int j = 0; j < 8; j++) s[j] = g_esrc[i + j];
        float e[8];
#pragma unroll
        for (int j = 0; j < 8; j++) e[j] = g_el[s[j] * HEADS + h];
        float4 f[8];
#pragma unroll
        for (int j = 0; j < 8; j++) f[j] = ldh4(&g_feath[(size_t)s[j] * FEAT_DIM + lane * 4]);
#pragma unroll
        for (int j = 0; j < 8; j++) {
            float ev = e[j] + erh;
            ev = ev > 0.f ? ev : NEG_SLOPE * ev;
            float w = __expf(ev);
            denom += w;
            acc.x += w * f[j].x;
            acc.y += w * f[j].y;
            acc.z += w * f[j].z;
            acc.w += w * f[j].w;
        }
    }
    for (; i < end; i++) {
        int s0 = g_esrc[i];
        float e0 = g_el[s0 * HEADS + h] + erh;
        e0 = e0 > 0.f ? e0 : NEG_SLOPE * e0;
        float w0 = __expf(e0);
        float4 f0 = ldh4(&g_feath[(size_t)s0 * FEAT_DIM + lane * 4]);
        denom += w0;
        acc.x += w0 * f0.x;
        acc.y += w0 * f0.y;
        acc.z += w0 * f0.z;
        acc.w += w0 * f0.w;
    }
    float inv = 0.25f / fmaxf(denom, 1e-9f);
    acc.x *= inv; acc.y *= inv; acc.z *= inv; acc.w *= inv;

#pragma unroll
    for (int o = 8; o <= 16; o <<= 1) {
        acc.x += __shfl_xor_sync(0xffffffffu, acc.x, o);
        acc.y += __shfl_xor_sync(0xffffffffu, acc.y, o);
        acc.z += __shfl_xor_sync(0xffffffffu, acc.z, o);
        acc.w += __shfl_xor_sync(0xffffffffu, acc.w, o);
    }
    if (lane < 8) {
        *(float4*)&out[(size_t)n * OUT_DIM + q * 4] = acc;
    }
}

// ---------------- launch ---------------------------------------------------
extern "C" void kernel_launch(void* const* d_in, const int* in_sizes, int n_in,
                              void* d_out, int out_size) {
    const float* x = (const float*)d_in[0];
    const float* W = (const float*)d_in[1];
    const float* attn_l = (const float*)d_in[2];
    const float* attn_r = (const float*)d_in[3];
    const int* src = (const int*)d_in[4];
    const int* dst = (const int*)d_in[5];
    float* out = (float*)d_out;

    static cudaStream_t s2 = nullptr;
    static cudaEvent_t evFork = nullptr, evJoin = nullptr;
    static void* deg_ptr = nullptr;
    if (s2 == nullptr) {
        cudaStreamCreateWithFlags(&s2, cudaStreamNonBlocking);
        cudaEventCreateWithFlags(&evFork, cudaEventDisableTiming);
        cudaEventCreateWithFlags(&evJoin, cudaEventDisableTiming);
        cudaGetSymbolAddress(&deg_ptr, g_deg);
        cudaFuncSetAttribute(gemm_mma_kernel, cudaFuncAttributeMaxDynamicSharedMemorySize, GEMM_SMEM);
    }

    cudaEventRecord(evFork, 0);
    cudaStreamWaitEvent(s2, evFork, 0);

    gemm_mma_kernel<<<GEMM_GRID, 256, GEMM_SMEM>>>(x, W, attn_l, attn_r);

    cudaMemsetAsync(deg_ptr, 0, N_NODES * sizeof(int), s2);
    hist_kernel<<<(N_EDGES / 4 + 255) / 256, 256, 0, s2>>>(dst);
    scan1_kernel<<<NB, SCAN_B, 0, s2>>>();
    scan3_kernel<<<(N_NODES + 255) / 256, 256, 0, s2>>>();
    scatter_kernel<<<(N_EDGES / 4 + 255) / 256, 256, 0, s2>>>(dst, src);

    cudaEventRecord(evJoin, s2);
    cudaStreamWaitEvent(0, evJoin, 0);
    aggregate_kernel<<<(N_NODES * 32 + 255) / 256, 256>>>(out);
}

// round 15
// speedup vs baseline: 1.4163x; 1.4163x over previous
#include <cuda_runtime.h>
#include <cuda_fp16.h>
#include <math_constants.h>
#include <cstdint>

#define N_NODES 100000
#define N_EDGES 1600000
#define IN_DIM 256
#define HEADS 4
#define OUT_DIM 32
#define FEAT_DIM 128
#define NEG_SLOPE 0.2f

#define SCAN_B 1024
#define NB ((N_NODES + SCAN_B - 1) / SCAN_B)   // 98
#define NTILES ((N_NODES + 127) / 128)         // 782
#define GEMM_GRID 148

// ---------------- scratch ---------------------------------------------------
__device__ __half g_feath[(size_t)N_NODES * FEAT_DIM];
__device__ float g_el[N_NODES * HEADS];
__device__ float g_er[N_NODES * HEADS];
__device__ int   g_deg[N_NODES];
__device__ int   g_off[N_NODES + 1];
__device__ int   g_cur[N_NODES];
__device__ int   g_esrc[N_EDGES];
__device__ int   g_bsums[128];

// ---------------- helpers ---------------------------------------------------
__device__ __forceinline__ uint32_t smem_u32(const void* p) {
    uint32_t a;
    asm("{ .reg .u64 t; cvta.to.shared.u64 t, %1; cvt.u32.u64 %0, t; }" : "=r"(a) : "l"(p));
    return a;
}
__device__ __forceinline__ void ldm_x4(uint32_t* r, uint32_t addr) {
    asm volatile("ldmatrix.sync.aligned.m8n8.x4.shared.b16 {%0,%1,%2,%3}, [%4];"
        : "=r"(r[0]), "=r"(r[1]), "=r"(r[2]), "=r"(r[3]) : "r"(addr));
}
__device__ __forceinline__ void ldm_x2(uint32_t* r, uint32_t addr) {
    asm volatile("ldmatrix.sync.aligned.m8n8.x2.shared.b16 {%0,%1}, [%2];"
        : "=r"(r[0]), "=r"(r[1]) : "r"(addr));
}
__device__ __forceinline__ void mma_f16(float* c, const uint32_t* a, const uint32_t* b) {
    asm volatile("mma.sync.aligned.m16n8k16.row.col.f32.f16.f16.f32 "
        "{%0,%1,%2,%3}, {%4,%5,%6,%7}, {%8,%9}, {%0,%1,%2,%3};"
        : "+f"(c[0]), "+f"(c[1]), "+f"(c[2]), "+f"(c[3])
        : "r"(a[0]), "r"(a[1]), "r"(a[2]), "r"(a[3]), "r"(b[0]), "r"(b[1]));
}
// unsinkable prefetch: volatile asm orders against the (volatile) ldmatrix/mma
__device__ __forceinline__ float4 ldg128v(const float4* p) {
    float4 v;
    asm volatile("ld.global.nc.v4.f32 {%0,%1,%2,%3}, [%4];"
        : "=f"(v.x), "=f"(v.y), "=f"(v.z), "=f"(v.w) : "l"(p));
    return v;
}

// ---------------- persistent single-fp16 HMMA GEMM --------------------------
// C = fp16(A) * fp16(W), fp32 accumulate; quantization total ~4e-4 (verified
// R10 rel_err 4.08e-4). A-prefetch issued via volatile LDG at loop top so
// ptxas cannot sink it below the compute (the R10 regression mechanism).
#define B_STRIDE 264
#define A_STRIDE 40
#define SM_B  0
#define SM_AH (128 * B_STRIDE * 2)                 // 67584
#define SM_ALS (SM_AH + 2 * 128 * A_STRIDE * 2)    // +20480
#define SM_ARS (SM_ALS + 512)
#define GEMM_SMEM (SM_ARS + 512)                   // ~89 KB

__device__ __forceinline__ void cvt16h(const float4* f, uint32_t* hw) {
    const float* ff = (const float*)f;
#pragma unroll
    for (int j = 0; j < 8; j++) {
        __half2 hp = __floats2half2_rn(ff[2 * j], ff[2 * j + 1]);
        hw[j] = *reinterpret_cast<uint32_t*>(&hp);
    }
}

__global__ __launch_bounds__(256, 1) void gemm_mma_kernel(const float* __restrict__ A,
                                                          const float* __restrict__ W,
                                                          const float* __restrict__ attn_l,
                                                          const float* __restrict__ attn_r) {
    extern __shared__ char smem[];
    __half* Bs = (__half*)(smem + SM_B);
    float* al_s = (float*)(smem + SM_ALS);
    float* ar_s = (float*)(smem + SM_ARS);

    const int tid = threadIdx.x;
    const int wid = tid >> 5;
    const int lane = tid & 31;
    const int warp_m = wid >> 1;
    const int warp_n = wid & 1;

    // ---- W load + fp16 convert into resident smem (once per CTA) ----
    for (int idx = tid; idx < IN_DIM * FEAT_DIM; idx += 256) {
        int k = idx >> 7, n = idx & 127;
        Bs[n * B_STRIDE + k] = __float2half_rn(W[idx]);
    }
    if (tid < 128) { al_s[tid] = attn_l[tid]; ar_s[tid] = attn_r[tid]; }

    const int ld_row = tid >> 1;
    const int ld_koff = (tid & 1) * 16;

    const uint32_t ah_b = smem_u32(smem + SM_AH);
    const uint32_t b_b  = smem_u32(smem + SM_B);
    const uint32_t abuf_bytes = 128 * A_STRIDE * 2;
    __syncthreads();

    for (int tile = blockIdx.x; tile < NTILES; tile += GEMM_GRID) {
        const int blockRow = tile * 128;
        int grow = blockRow + ld_row;
        if (grow >= N_NODES) grow = N_NODES - 1;
        const float4* aptr = (const float4*)(A + (size_t)grow * IN_DIM + ld_koff);

        float c[2][8][4];
#pragma unroll
        for (int mt = 0; mt < 2; mt++)
#pragma unroll
            for (int nt = 0; nt < 8; nt++)
#pragma unroll
                for (int j = 0; j < 4; j++) c[mt][nt][j] = 0.f;

        // ---- prologue: chunk 0 -> buf 0 ----
        {
            float4 f[4];
#pragma unroll
            for (int j = 0; j < 4; j++) f[j] = ldg128v(aptr + j);
            uint32_t hw[8];
            cvt16h(f, hw);
            __half* Ah0 = (__half*)(smem + SM_AH);
            *(uint4*)&Ah0[ld_row * A_STRIDE + ld_koff]     = make_uint4(hw[0], hw[1], hw[2], hw[3]);
            *(uint4*)&Ah0[ld_row * A_STRIDE + ld_koff + 8] = make_uint4(hw[4], hw[5], hw[6], hw[7]);
        }
        __syncthreads();

        for (int kc = 0; kc < 8; kc++) {
            // prefetch next chunk FIRST, via unsinkable volatile LDG
            float4 fn[4];
            if (kc < 7) {
#pragma unroll
                for (int j = 0; j < 4; j++) fn[j] = ldg128v(aptr + (kc + 1) * 8 + j);
            }
            const uint32_t abase_h = ah_b + (kc & 1) * abuf_bytes;

#pragma unroll
            for (int ks = 0; ks < 2; ks++) {
                const int k0 = ks * 16;
                uint32_t ah[2][4];
#pragma unroll
                for (int mt = 0; mt < 2; mt++) {
                    int r = warp_m * 32 + mt * 16 + (lane & 15);
                    int cc = k0 + ((lane >> 4) & 1) * 8;
                    uint32_t off = (uint32_t)(r * A_STRIDE + cc) * 2;
                    ldm_x4(ah[mt], abase_h + off);
                }
                uint32_t bf[8][2];
#pragma unroll
                for (int nt = 0; nt < 8; nt++) {
                    int n = warp_n * 64 + nt * 8 + (lane & 7);
                    int cc = kc * 32 + k0 + ((lane >> 3) & 1) * 8;
                    uint32_t off = (uint32_t)(n * B_STRIDE + cc) * 2;
                    ldm_x2(bf[nt], b_b + off);
                }
#pragma unroll
                for (int mt = 0; mt < 2; mt++)
#pragma unroll
                    for (int nt = 0; nt < 8; nt++) {
                        mma_f16(c[mt][nt], ah[mt], bf[nt]);
                    }
            }

            if (kc < 7) {
                uint32_t hw[8];
                cvt16h(fn, hw);
                __half* Ahn = (__half*)(smem + SM_AH + ((kc + 1) & 1) * abuf_bytes);
                *(uint4*)&Ahn[ld_row * A_STRIDE + ld_koff]     = make_uint4(hw[0], hw[1], hw[2], hw[3]);
                *(uint4*)&Ahn[ld_row * A_STRIDE + ld_koff + 8] = make_uint4(hw[4], hw[5], hw[6], hw[7]);
            }
            __syncthreads();
        }

        // ---- epilogue: store feat (fp16) + fused el/er (fp32) ----
#pragma unroll
        for (int mt = 0; mt < 2; mt++) {
            float el_[2][2] = {{0.f, 0.f}, {0.f, 0.f}};
            float er_[2][2] = {{0.f, 0.f}, {0.f, 0.f}};
            int row0 = blockRow + warp_m * 32 + mt * 16 + (lane >> 2);
#pragma unroll
            for (int nt = 0; nt < 8; nt++) {
                int hl = nt >> 2;
                int col = warp_n * 64 + nt * 8 + (lane & 3) * 2;
                float c0 = c[mt][nt][0], c1 = c[mt][nt][1];
                float c2 = c[mt][nt][2], c3 = c[mt][nt][3];
                float a0 = al_s[col], a1 = al_s[col + 1];
                float r0 = ar_s[col], r1 = ar_s[col + 1];
                el_[0][hl] += c0 * a0 + c1 * a1;
                er_[0][hl] += c0 * r0 + c1 * r1;
                el_[1][hl] += c2 * a0 + c3 * a1;
                er_[1][hl] += c2 * r0 + c3 * r1;
                if (row0 < N_NODES)
                    *(__half2*)&g_feath[(size_t)row0 * FEAT_DIM + col] = __floats2half2_rn(c0, c1);
                if (row0 + 8 < N_NODES)
                    *(__half2*)&g_feath[(size_t)(row0 + 8) * FEAT_DIM + col] = __floats2half2_rn(c2, c3);
            }
#pragma unroll
            for (int rh = 0; rh < 2; rh++)
#pragma unroll
                for (int hl = 0; hl < 2; hl++) {
                    float v = el_[rh][hl];
                    float w = er_[rh][hl];
                    v += __shfl_xor_sync(0xffffffffu, v, 1);
                    v += __shfl_xor_sync(0xffffffffu, v, 2);
                    w += __shfl_xor_sync(0xffffffffu, w, 1);
                    w += __shfl_xor_sync(0xffffffffu, w, 2);
                    int row = row0 + rh * 8;
                    if ((lane & 3) == 0 && row < N_NODES) {
                        g_el[row * HEADS + warp_n * 2 + hl] = v;
                        g_er[row * HEADS + warp_n * 2 + hl] = w;
                    }
                }
        }
    }
}

// ---------------- CSR build ------------------------------------------------
__global__ void hist_kernel(const int* __restrict__ dst) {
    int i = blockIdx.x * blockDim.x + threadIdx.x;
    if (i < N_EDGES / 4) {
        int4 d = ((const int4*)dst)[i];
        atomicAdd(&g_deg[d.x], 1);
        atomicAdd(&g_deg[d.y], 1);
        atomicAdd(&g_deg[d.z], 1);
        atomicAdd(&g_deg[d.w], 1);
    }
}

__global__ __launch_bounds__(SCAN_B) void scan1_kernel() {
    __shared__ int wsum[32];
    int i = blockIdx.x * SCAN_B + threadIdx.x;
    int lane = threadIdx.x & 31;
    int wid = threadIdx.x >> 5;
    int v = (i < N_NODES) ? g_deg[i] : 0;
    int x = v;
#pragma unroll
    for (int o = 1; o < 32; o <<= 1) {
        int y = __shfl_up_sync(0xffffffffu, x, o);
        if (lane >= o) x += y;
    }
    if (lane == 31) wsum[wid] = x;
    __syncthreads();
    if (threadIdx.x < 32) {
        int w = wsum[threadIdx.x];
#pragma unroll
        for (int o = 1; o < 32; o <<= 1) {
            int y = __shfl_up_sync(0xffffffffu, w, o);
            if ((int)threadIdx.x >= o) w += y;
        }
        wsum[threadIdx.x] = w;
    }
    __syncthreads();
    int base = wid ? wsum[wid - 1] : 0;
    int incl = x + base;
    if (i < N_NODES) g_off[i] = incl;
    if (threadIdx.x == SCAN_B - 1) g_bsums[blockIdx.x] = incl;
}

__global__ void scan2_kernel() {
    __shared__ int ws[4];
    int t = threadIdx.x;
    int lane = t & 31;
    int wid = t >> 5;
    int v = (t < NB) ? g_bsums[t] : 0;
    int x = v;
#pragma unroll
    for (int o = 1; o < 32; o <<= 1) {
        int y = __shfl_up_sync(0xffffffffu, x, o);
        if (lane >= o) x += y;
    }
    if (lane == 31) ws[wid] = x;
    __syncthreads();
    int base = 0;
    for (int w = 0; w < wid; w++) base += ws[w];
    g_bsums[t] = x + base;
}

__global__ void scan3_kernel() {
    int i = blockIdx.x * blockDim.x + threadIdx.x;
    if (i < N_NODES) {
        int b = i >> 10;
        int add = b ? g_bsums[b - 1] : 0;
        int incl = g_off[i] + add;
        int excl = incl - g_deg[i];
        g_off[i] = excl;
        g_cur[i] = excl;
        if (i == 0) g_off[N_NODES] = g_bsums[NB - 1];
    }
}

__global__ void scatter_kernel(const int* __restrict__ dst, const int* __restrict__ src) {
    int i = blockIdx.x * blockDim.x + threadIdx.x;
    if (i < N_EDGES / 4) {
        int4 d = ((const int4*)dst)[i];
        int4 s = ((const int4*)src)[i];
        g_esrc[atomicAdd(&g_cur[d.x], 1)] = s.x;
        g_esrc[atomicAdd(&g_cur[d.y], 1)] = s.y;
        g_esrc[atomicAdd(&g_cur[d.z], 1)] = s.z;
        g_esrc[atomicAdd(&g_cur[d.w], 1)] = s.w;
    }
}

// ---------------- fused single-pass softmax + aggregation (8-deep MLP) -----
__device__ __forceinline__ float4 ldh4(const __half* p) {
    uint2 u = *(const uint2*)p;
    __half2 h0 = *reinterpret_cast<__half2*>(&u.x);
    __half2 h1 = *reinterpret_cast<__half2*>(&u.y);
    float2 f0 = __half22float2(h0);
    float2 f1 = __half22float2(h1);
    return make_float4(f0.x, f0.y, f1.x, f1.y);
}

__global__ __launch_bounds__(256) void aggregate_kernel(float* __restrict__ out) {
    int n = (blockIdx.x * blockDim.x + threadIdx.x) >> 5;
    int lane = threadIdx.x & 31;
    if (n >= N_NODES) return;
    int h = lane >> 3;
    int q = lane & 7;

    int begin = g_off[n];
    int end = g_off[n + 1];
    float erh = g_er[n * HEADS + h];

    float4 acc = make_float4(0.f, 0.f, 0.f, 0.f);
    float denom = 0.f;
    int i = begin;
    for (; i + 8 <= end; i += 8) {
        int s[8];
#pragma unroll
        for (int j = 0; j < 8; j++) s[j] = g_esrc[i + j];
        float e[8];
#pragma unroll
        for (int j = 0; j < 8; j++) e[j] = g_el[s[j] * HEADS + h];
        float4 f[8];
#pragma unroll
        for (int j = 0; j < 8; j++) f[j] = ldh4(&g_feath[(size_t)s[j] * FEAT_DIM + lane * 4]);
#pragma unroll
        for (int j = 0; j < 8; j++) {
            float ev = e[j] + erh;
            ev = ev > 0.f ? ev : NEG_SLOPE * ev;
            float w = __expf(ev);
            denom += w;
            acc.x += w * f[j].x;
            acc.y += w * f[j].y;
            acc.z += w * f[j].z;
            acc.w += w * f[j].w;
        }
    }
    for (; i < end; i++) {
        int s0 = g_esrc[i];
        float e0 = g_el[s0 * HEADS + h] + erh;
        e0 = e0 > 0.f ? e0 : NEG_SLOPE * e0;
        float w0 = __expf(e0);
        float4 f0 = ldh4(&g_feath[(size_t)s0 * FEAT_DIM + lane * 4]);
        denom += w0;
        acc.x += w0 * f0.x;
        acc.y += w0 * f0.y;
        acc.z += w0 * f0.z;
        acc.w += w0 * f0.w;
    }
    float inv = 0.25f / fmaxf(denom, 1e-9f);
    acc.x *= inv; acc.y *= inv; acc.z *= inv; acc.w *= inv;

#pragma unroll
    for (int o = 8; o <= 16; o <<= 1) {
        acc.x += __shfl_xor_sync(0xffffffffu, acc.x, o);
        acc.y += __shfl_xor_sync(0xffffffffu, acc.y, o);
        acc.z += __shfl_xor_sync(0xffffffffu, acc.z, o);
        acc.w += __shfl_xor_sync(0xffffffffu, acc.w, o);
    }
    if (lane < 8) {
        *(float4*)&out[(size_t)n * OUT_DIM + q * 4] = acc;
    }
}

// ---------------- launch ---------------------------------------------------
extern "C" void kernel_launch(void* const* d_in, const int* in_sizes, int n_in,
                              void* d_out, int out_size) {
    const float* x = (const float*)d_in[0];
    const float* W = (const float*)d_in[1];
    const float* attn_l = (const float*)d_in[2];
    const float* attn_r = (const float*)d_in[3];
    const int* src = (const int*)d_in[4];
    const int* dst = (const int*)d_in[5];
    float* out = (float*)d_out;

    static cudaStream_t s2 = nullptr;
    static cudaEvent_t evFork = nullptr, evJoin = nullptr;
    static void* deg_ptr = nullptr;
    if (s2 == nullptr) {
        cudaStreamCreateWithFlags(&s2, cudaStreamNonBlocking);
        cudaEventCreateWithFlags(&evFork, cudaEventDisableTiming);
        cudaEventCreateWithFlags(&evJoin, cudaEventDisableTiming);
        cudaGetSymbolAddress(&deg_ptr, g_deg);
        cudaFuncSetAttribute(gemm_mma_kernel, cudaFuncAttributeMaxDynamicSharedMemorySize, GEMM_SMEM);
    }

    cudaEventRecord(evFork, 0);
    cudaStreamWaitEvent(s2, evFork, 0);

    gemm_mma_kernel<<<GEMM_GRID, 256, GEMM_SMEM>>>(x, W, attn_l, attn_r);

    cudaMemsetAsync(deg_ptr, 0, N_NODES * sizeof(int), s2);
    hist_kernel<<<(N_EDGES / 4 + 255) / 256, 256, 0, s2>>>(dst);
    scan1_kernel<<<NB, SCAN_B, 0, s2>>>();
    scan2_kernel<<<1, 128, 0, s2>>>();
    scan3_kernel<<<(N_NODES + 255) / 256, 256, 0, s2>>>();
    scatter_kernel<<<(N_EDGES / 4 + 255) / 256, 256, 0, s2>>>(dst, src);

    cudaEventRecord(evJoin, s2);
    cudaStreamWaitEvent(0, evJoin, 0);
    aggregate_kernel<<<(N_NODES * 32 + 255) / 256, 256>>>(out);
}

// round 16
// speedup vs baseline: 1.4391x; 1.0161x over previous
#include <cuda_runtime.h>
#include <cuda_fp16.h>
#include <math_constants.h>
#include <cstdint>

#define N_NODES 100000
#define N_EDGES 1600000
#define IN_DIM 256
#define HEADS 4
#define OUT_DIM 32
#define FEAT_DIM 128
#define NEG_SLOPE 0.2f

#define SCAN_B 1024
#define NB ((N_NODES + SCAN_B - 1) / SCAN_B)   // 98
#define NTILES ((N_NODES + 127) / 128)         // 782
#define GEMM_GRID 148

// ---------------- scratch ---------------------------------------------------
__device__ __half g_feath[(size_t)N_NODES * FEAT_DIM];
__device__ float g_el[N_NODES * HEADS];
__device__ float g_er[N_NODES * HEADS];
__device__ int   g_deg[N_NODES];     // zero-init at load; re-zeroed by scan3 each run
__device__ int   g_off[N_NODES + 1];
__device__ int   g_cur[N_NODES];
__device__ int   g_esrc[N_EDGES];
__device__ int   g_bsums[128];

// ---------------- helpers ---------------------------------------------------
__device__ __forceinline__ uint32_t smem_u32(const void* p) {
    uint32_t a;
    asm("{ .reg .u64 t; cvta.to.shared.u64 t, %1; cvt.u32.u64 %0, t; }" : "=r"(a) : "l"(p));
    return a;
}
__device__ __forceinline__ void ldm_x4(uint32_t* r, uint32_t addr) {
    asm volatile("ldmatrix.sync.aligned.m8n8.x4.shared.b16 {%0,%1,%2,%3}, [%4];"
        : "=r"(r[0]), "=r"(r[1]), "=r"(r[2]), "=r"(r[3]) : "r"(addr));
}
__device__ __forceinline__ void ldm_x2(uint32_t* r, uint32_t addr) {
    asm volatile("ldmatrix.sync.aligned.m8n8.x2.shared.b16 {%0,%1}, [%2];"
        : "=r"(r[0]), "=r"(r[1]) : "r"(addr));
}
__device__ __forceinline__ void mma_f16(float* c, const uint32_t* a, const uint32_t* b) {
    asm volatile("mma.sync.aligned.m16n8k16.row.col.f32.f16.f16.f32 "
        "{%0,%1,%2,%3}, {%4,%5,%6,%7}, {%8,%9}, {%0,%1,%2,%3};"
        : "+f"(c[0]), "+f"(c[1]), "+f"(c[2]), "+f"(c[3])
        : "r"(a[0]), "r"(a[1]), "r"(a[2]), "r"(a[3]), "r"(b[0]), "r"(b[1]));
}
// unsinkable prefetch: volatile asm orders against the (volatile) ldmatrix/mma
__device__ __forceinline__ float4 ldg128v(const float4* p) {
    float4 v;
    asm volatile("ld.global.nc.v4.f32 {%0,%1,%2,%3}, [%4];"
        : "=f"(v.x), "=f"(v.y), "=f"(v.z), "=f"(v.w) : "l"(p));
    return v;
}

// ---------------- persistent single-fp16 HMMA GEMM --------------------------
#define B_STRIDE 264
#define A_STRIDE 40
#define SM_B  0
#define SM_AH (128 * B_STRIDE * 2)                 // 67584
#define SM_ALS (SM_AH + 2 * 128 * A_STRIDE * 2)    // +20480
#define SM_ARS (SM_ALS + 512)
#define GEMM_SMEM (SM_ARS + 512)                   // ~89 KB

__device__ __forceinline__ void cvt16h(const float4* f, uint32_t* hw) {
    const float* ff = (const float*)f;
#pragma unroll
    for (int j = 0; j < 8; j++) {
        __half2 hp = __floats2half2_rn(ff[2 * j], ff[2 * j + 1]);
        hw[j] = *reinterpret_cast<uint32_t*>(&hp);
    }
}

__global__ __launch_bounds__(256, 1) void gemm_mma_kernel(const float* __restrict__ A,
                                                          const float* __restrict__ W,
                                                          const float* __restrict__ attn_l,
                                                          const float* __restrict__ attn_r) {
    extern __shared__ char smem[];
    __half* Bs = (__half*)(smem + SM_B);
    float* al_s = (float*)(smem + SM_ALS);
    float* ar_s = (float*)(smem + SM_ARS);

    const int tid = threadIdx.x;
    const int wid = tid >> 5;
    const int lane = tid & 31;
    const int warp_m = wid >> 1;
    const int warp_n = wid & 1;

    for (int idx = tid; idx < IN_DIM * FEAT_DIM; idx += 256) {
        int k = idx >> 7, n = idx & 127;
        Bs[n * B_STRIDE + k] = __float2half_rn(W[idx]);
    }
    if (tid < 128) { al_s[tid] = attn_l[tid]; ar_s[tid] = attn_r[tid]; }

    const int ld_row = tid >> 1;
    const int ld_koff = (tid & 1) * 16;

    const uint32_t ah_b = smem_u32(smem + SM_AH);
    const uint32_t b_b  = smem_u32(smem + SM_B);
    const uint32_t abuf_bytes = 128 * A_STRIDE * 2;
    __syncthreads();

    for (int tile = blockIdx.x; tile < NTILES; tile += GEMM_GRID) {
        const int blockRow = tile * 128;
        int grow = blockRow + ld_row;
        if (grow >= N_NODES) grow = N_NODES - 1;
        const float4* aptr = (const float4*)(A + (size_t)grow * IN_DIM + ld_koff);

        float c[2][8][4];
#pragma unroll
        for (int mt = 0; mt < 2; mt++)
#pragma unroll
            for (int nt = 0; nt < 8; nt++)
#pragma unroll
                for (int j = 0; j < 4; j++) c[mt][nt][j] = 0.f;

        {
            float4 f[4];
#pragma unroll
            for (int j = 0; j < 4; j++) f[j] = ldg128v(aptr + j);
            uint32_t hw[8];
            cvt16h(f, hw);
            __half* Ah0 = (__half*)(smem + SM_AH);
            *(uint4*)&Ah0[ld_row * A_STRIDE + ld_koff]     = make_uint4(hw[0], hw[1], hw[2], hw[3]);
            *(uint4*)&Ah0[ld_row * A_STRIDE + ld_koff + 8] = make_uint4(hw[4], hw[5], hw[6], hw[7]);
        }
        __syncthreads();

        for (int kc = 0; kc < 8; kc++) {
            float4 fn[4];
            if (kc < 7) {
#pragma unroll
                for (int j = 0; j < 4; j++) fn[j] = ldg128v(aptr + (kc + 1) * 8 + j);
            }
            const uint32_t abase_h = ah_b + (kc & 1) * abuf_bytes;

#pragma unroll
            for (int ks = 0; ks < 2; ks++) {
                const int k0 = ks * 16;
                uint32_t ah[2][4];
#pragma unroll
                for (int mt = 0; mt < 2; mt++) {
                    int r = warp_m * 32 + mt * 16 + (lane & 15);
                    int cc = k0 + ((lane >> 4) & 1) * 8;
                    uint32_t off = (uint32_t)(r * A_STRIDE + cc) * 2;
                    ldm_x4(ah[mt], abase_h + off);
                }
                uint32_t bf[8][2];
#pragma unroll
                for (int nt = 0; nt < 8; nt++) {
                    int n = warp_n * 64 + nt * 8 + (lane & 7);
                    int cc = kc * 32 + k0 + ((lane >> 3) & 1) * 8;
                    uint32_t off = (uint32_t)(n * B_STRIDE + cc) * 2;
                    ldm_x2(bf[nt], b_b + off);
                }
#pragma unroll
                for (int mt = 0; mt < 2; mt++)
#pragma unroll
                    for (int nt = 0; nt < 8; nt++) {
                        mma_f16(c[mt][nt], ah[mt], bf[nt]);
                    }
            }

            if (kc < 7) {
                uint32_t hw[8];
                cvt16h(fn, hw);
                __half* Ahn = (__half*)(smem + SM_AH + ((kc + 1) & 1) * abuf_bytes);
                *(uint4*)&Ahn[ld_row * A_STRIDE + ld_koff]     = make_uint4(hw[0], hw[1], hw[2], hw[3]);
                *(uint4*)&Ahn[ld_row * A_STRIDE + ld_koff + 8] = make_uint4(hw[4], hw[5], hw[6], hw[7]);
            }
            __syncthreads();
        }

        // ---- epilogue: store feat (fp16) + fused el/er (fp32) ----
#pragma unroll
        for (int mt = 0; mt < 2; mt++) {
            float el_[2][2] = {{0.f, 0.f}, {0.f, 0.f}};
            float er_[2][2] = {{0.f, 0.f}, {0.f, 0.f}};
            int row0 = blockRow + warp_m * 32 + mt * 16 + (lane >> 2);
#pragma unroll
            for (int nt = 0; nt < 8; nt++) {
                int hl = nt >> 2;
                int col = warp_n * 64 + nt * 8 + (lane & 3) * 2;
                float c0 = c[mt][nt][0], c1 = c[mt][nt][1];
                float c2 = c[mt][nt][2], c3 = c[mt][nt][3];
                float a0 = al_s[col], a1 = al_s[col + 1];
                float r0 = ar_s[col], r1 = ar_s[col + 1];
                el_[0][hl] += c0 * a0 + c1 * a1;
                er_[0][hl] += c0 * r0 + c1 * r1;
                el_[1][hl] += c2 * a0 + c3 * a1;
                er_[1][hl] += c2 * r0 + c3 * r1;
                if (row0 < N_NODES)
                    *(__half2*)&g_feath[(size_t)row0 * FEAT_DIM + col] = __floats2half2_rn(c0, c1);
                if (row0 + 8 < N_NODES)
                    *(__half2*)&g_feath[(size_t)(row0 + 8) * FEAT_DIM + col] = __floats2half2_rn(c2, c3);
            }
#pragma unroll
            for (int rh = 0; rh < 2; rh++)
#pragma unroll
                for (int hl = 0; hl < 2; hl++) {
                    float v = el_[rh][hl];
                    float w = er_[rh][hl];
                    v += __shfl_xor_sync(0xffffffffu, v, 1);
                    v += __shfl_xor_sync(0xffffffffu, v, 2);
                    w += __shfl_xor_sync(0xffffffffu, w, 1);
                    w += __shfl_xor_sync(0xffffffffu, w, 2);
                    int row = row0 + rh * 8;
                    if ((lane & 3) == 0 && row < N_NODES) {
                        g_el[row * HEADS + warp_n * 2 + hl] = v;
                        g_er[row * HEADS + warp_n * 2 + hl] = w;
                    }
                }
        }
    }
}

// ---------------- CSR build ------------------------------------------------
// g_deg enters each run zeroed (module init on first run; scan3 re-zeroes it
// after its final read, so every complete run restores the invariant).
__global__ void hist_kernel(const int* __restrict__ dst) {
    int i = blockIdx.x * blockDim.x + threadIdx.x;
    if (i < N_EDGES / 4) {
        int4 d = ((const int4*)dst)[i];
        atomicAdd(&g_deg[d.x], 1);
        atomicAdd(&g_deg[d.y], 1);
        atomicAdd(&g_deg[d.z], 1);
        atomicAdd(&g_deg[d.w], 1);
    }
}

__global__ __launch_bounds__(SCAN_B) void scan1_kernel() {
    __shared__ int wsum[32];
    int i = blockIdx.x * SCAN_B + threadIdx.x;
    int lane = threadIdx.x & 31;
    int wid = threadIdx.x >> 5;
    int v = (i < N_NODES) ? g_deg[i] : 0;
    int x = v;
#pragma unroll
    for (int o = 1; o < 32; o <<= 1) {
        int y = __shfl_up_sync(0xffffffffu, x, o);
        if (lane >= o) x += y;
    }
    if (lane == 31) wsum[wid] = x;
    __syncthreads();
    if (threadIdx.x < 32) {
        int w = wsum[threadIdx.x];
#pragma unroll
        for (int o = 1; o < 32; o <<= 1) {
            int y = __shfl_up_sync(0xffffffffu, w, o);
            if ((int)threadIdx.x >= o) w += y;
        }
        wsum[threadIdx.x] = w;
    }
    __syncthreads();
    int base = wid ? wsum[wid - 1] : 0;
    int incl = x + base;
    if (i < N_NODES) g_off[i] = incl;
    if (threadIdx.x == SCAN_B - 1) g_bsums[blockIdx.x] = incl;
}

// scan3 with inlined 98-element block-sums scan (replaces scan2) and g_deg
// re-zero for the next graph replay.
__global__ void scan3_kernel() {
    __shared__ int bpre[128];
    __shared__ int wtot[4];
    int t = threadIdx.x;
    int lane = t & 31;
    int w = t >> 5;
    int x = 0;
    if (t < 128) {
        x = (t < NB) ? g_bsums[t] : 0;
#pragma unroll
        for (int o = 1; o < 32; o <<= 1) {
            int y = __shfl_up_sync(0xffffffffu, x, o);
            if (lane >= o) x += y;
        }
        if (lane == 31) wtot[w] = x;
    }
    __syncthreads();
    if (t < 128) {
        int base = 0;
        for (int ww = 0; ww < w; ww++) base += wtot[ww];
        bpre[t] = x + base;
    }
    __syncthreads();
    int i = blockIdx.x * blockDim.x + t;
    if (i < N_NODES) {
        int b = i >> 10;
        int add = b ? bpre[b - 1] : 0;
        int incl = g_off[i] + add;
        int deg = g_deg[i];
        int excl = incl - deg;
        g_off[i] = excl;
        g_cur[i] = excl;
        g_deg[i] = 0;                 // restore invariant for next replay
        if (i == 0) g_off[N_NODES] = bpre[NB - 1];
    }
}

__global__ void scatter_kernel(const int* __restrict__ dst, const int* __restrict__ src) {
    int i = blockIdx.x * blockDim.x + threadIdx.x;
    if (i < N_EDGES / 4) {
        int4 d = ((const int4*)dst)[i];
        int4 s = ((const int4*)src)[i];
        g_esrc[atomicAdd(&g_cur[d.x], 1)] = s.x;
        g_esrc[atomicAdd(&g_cur[d.y], 1)] = s.y;
        g_esrc[atomicAdd(&g_cur[d.z], 1)] = s.z;
        g_esrc[atomicAdd(&g_cur[d.w], 1)] = s.w;
    }
}

// ---------------- fused single-pass softmax + aggregation (8-deep MLP) -----
__device__ __forceinline__ float4 ldh4(const __half* p) {
    uint2 u = *(const uint2*)p;
    __half2 h0 = *reinterpret_cast<__half2*>(&u.x);
    __half2 h1 = *reinterpret_cast<__half2*>(&u.y);
    float2 f0 = __half22float2(h0);
    float2 f1 = __half22float2(h1);
    return make_float4(f0.x, f0.y, f1.x, f1.y);
}

__global__ __launch_bounds__(256) void aggregate_kernel(float* __restrict__ out) {
    int n = (blockIdx.x * blockDim.x + threadIdx.x) >> 5;
    int lane = threadIdx.x & 31;
    if (n >= N_NODES) return;
    int h = lane >> 3;
    int q = lane & 7;

    int begin = g_off[n];
    int end = g_off[n + 1];
    float erh = g_er[n * HEADS + h];

    float4 acc = make_float4(0.f, 0.f, 0.f, 0.f);
    float denom = 0.f;
    int i = begin;
    for (; i + 8 <= end; i += 8) {
        int s[8];
#pragma unroll
        for (int j = 0; j < 8; j++) s[j] = g_esrc[i + j];
        float e[8];
#pragma unroll
        for (int j = 0; j < 8; j++) e[j] = g_el[s[j] * HEADS + h];
        float4 f[8];
#pragma unroll
        for (int j = 0; j < 8; j++) f[j] = ldh4(&g_feath[(size_t)s[j] * FEAT_DIM + lane * 4]);
#pragma unroll
        for (int j = 0; j < 8; j++) {
            float ev = e[j] + erh;
            ev = ev > 0.f ? ev : NEG_SLOPE * ev;
            float w = __expf(ev);
            denom += w;
            acc.x += w * f[j].x;
            acc.y += w * f[j].y;
            acc.z += w * f[j].z;
            acc.w += w * f[j].w;
        }
    }
    for (; i < end; i++) {
        int s0 = g_esrc[i];
        float e0 = g_el[s0 * HEADS + h] + erh;
        e0 = e0 > 0.f ? e0 : NEG_SLOPE * e0;
        float w0 = __expf(e0);
        float4 f0 = ldh4(&g_feath[(size_t)s0 * FEAT_DIM + lane * 4]);
        denom += w0;
        acc.x += w0 * f0.x;
        acc.y += w0 * f0.y;
        acc.z += w0 * f0.z;
        acc.w += w0 * f0.w;
    }
    float inv = 0.25f / fmaxf(denom, 1e-9f);
    acc.x *= inv; acc.y *= inv; acc.z *= inv; acc.w *= inv;

#pragma unroll
    for (int o = 8; o <= 16; o <<= 1) {
        acc.x += __shfl_xor_sync(0xffffffffu, acc.x, o);
        acc.y += __shfl_xor_sync(0xffffffffu, acc.y, o);
        acc.z += __shfl_xor_sync(0xffffffffu, acc.z, o);
        acc.w += __shfl_xor_sync(0xffffffffu, acc.w, o);
    }
    if (lane < 8) {
        *(float4*)&out[(size_t)n * OUT_DIM + q * 4] = acc;
    }
}

// ---------------- launch ---------------------------------------------------
extern "C" void kernel_launch(void* const* d_in, const int* in_sizes, int n_in,
                              void* d_out, int out_size) {
    const float* x = (const float*)d_in[0];
    const float* W = (const float*)d_in[1];
    const float* attn_l = (const float*)d_in[2];
    const float* attn_r = (const float*)d_in[3];
    const int* src = (const int*)d_in[4];
    const int* dst = (const int*)d_in[5];
    float* out = (float*)d_out;

    static cudaStream_t s2 = nullptr;
    static cudaEvent_t evFork = nullptr, evJoin = nullptr;
    if (s2 == nullptr) {
        cudaStreamCreateWithFlags(&s2, cudaStreamNonBlocking);
        cudaEventCreateWithFlags(&evFork, cudaEventDisableTiming);
        cudaEventCreateWithFlags(&evJoin, cudaEventDisableTiming);
        cudaFuncSetAttribute(gemm_mma_kernel, cudaFuncAttributeMaxDynamicSharedMemorySize, GEMM_SMEM);
    }

    cudaEventRecord(evFork, 0);
    cudaStreamWaitEvent(s2, evFork, 0);

    gemm_mma_kernel<<<GEMM_GRID, 256, GEMM_SMEM>>>(x, W, attn_l, attn_r);

    hist_kernel<<<(N_EDGES / 4 + 255) / 256, 256, 0, s2>>>(dst);
    scan1_kernel<<<NB, SCAN_B, 0, s2>>>();
    scan3_kernel<<<(N_NODES + 255) / 256, 256, 0, s2>>>();
    scatter_kernel<<<(N_EDGES / 4 + 255) / 256, 256, 0, s2>>>(dst, src);

    cudaEventRecord(evJoin, s2);
    cudaStreamWaitEvent(0, evJoin, 0);
    aggregate_kernel<<<(N_NODES * 32 + 255) / 256, 256>>>(out);
}